// round 4
// baseline (speedup 1.0000x reference)
#include <cuda_runtime.h>
#include <cuda_bf16.h>
#include <math.h>

// ---------------- problem constants ----------------
#define Bb   4
#define Nn   4096
#define Dd   1024
#define Hh   16
#define Ss   512
#define DH   64
#define DFF  4096
#define BH   (Bb*Hh)

// ---------------- scratch (device globals; no mallocs allowed) ----------------
__device__ float g_xln [(size_t)Bb*Nn*Dd];        // 64 MB
__device__ float g_rt  [(size_t)BH*Ss*Nn];        // 512 MB  scores transposed (z, s, n)
__device__ float g_cmax[BH*Ss];
__device__ float g_cinv[BH*Ss];
__device__ float g_rowsc[BH*Nn];
__device__ float g_ocat[(size_t)Bb*Nn*Dd];        // 64 MB
__device__ float g_y   [(size_t)Bb*Nn*Dd];        // 64 MB
__device__ float g_hln [(size_t)Bb*Nn*Dd];        // 64 MB
__device__ float g_hact[(size_t)Bb*Nn*DFF];       // 256 MB

// ---------------- helpers ----------------
__device__ __forceinline__ float gelu_f(float x) {
    return 0.5f * x * (1.f + erff(x * 0.70710678118654752f));
}

// ---------------- LayerNorm: one block per row of 1024 ----------------
__global__ void ln_kernel(const float* __restrict__ x, const float* __restrict__ g,
                          const float* __restrict__ b, float* __restrict__ o) {
    __shared__ float sh[64];
    long long row = blockIdx.x;
    const float4* xr = reinterpret_cast<const float4*>(x + row * Dd);
    int t = threadIdx.x;                       // 256 threads, 4 elems each
    float4 v = xr[t];
    float s  = v.x + v.y + v.z + v.w;
    float ss = v.x*v.x + v.y*v.y + v.z*v.z + v.w*v.w;
    #pragma unroll
    for (int off = 16; off; off >>= 1) {
        s  += __shfl_xor_sync(0xffffffffu, s,  off);
        ss += __shfl_xor_sync(0xffffffffu, ss, off);
    }
    int w = t >> 5;
    if ((t & 31) == 0) { sh[w] = s; sh[32 + w] = ss; }
    __syncthreads();
    if (t < 32) {
        float a = (t < 8) ? sh[t]      : 0.f;
        float c = (t < 8) ? sh[32 + t] : 0.f;
        #pragma unroll
        for (int off = 4; off; off >>= 1) {
            a += __shfl_xor_sync(0xffffffffu, a, off);
            c += __shfl_xor_sync(0xffffffffu, c, off);
        }
        if (t == 0) { sh[0] = a; sh[1] = c; }
    }
    __syncthreads();
    float mean = sh[0] * (1.f / Dd);
    float var  = sh[1] * (1.f / Dd) - mean * mean;
    float r = rsqrtf(var + 1e-5f);
    float4 gv = reinterpret_cast<const float4*>(g)[t];
    float4 bv = reinterpret_cast<const float4*>(b)[t];
    float4 ov;
    ov.x = (v.x - mean) * r * gv.x + bv.x;
    ov.y = (v.y - mean) * r * gv.y + bv.y;
    ov.z = (v.z - mean) * r * gv.z + bv.z;
    ov.w = (v.w - mean) * r * gv.w + bv.w;
    reinterpret_cast<float4*>(o + row * Dd)[t] = ov;
}

// ---------------- softmax stats over N (rows of Rt): one block per (z,s) ----------------
__global__ void softmax_stats(const float* __restrict__ Rt,
                              float* __restrict__ cmax, float* __restrict__ cinv) {
    __shared__ float sh[32];
    long long row = blockIdx.x;                // 0 .. BH*S-1
    const float4* r4 = reinterpret_cast<const float4*>(Rt + row * Nn);
    int t = threadIdx.x;                       // 256 threads
    float4 vv[4];
    float lm = -1e30f;
    #pragma unroll
    for (int i = 0; i < 4; i++) {
        vv[i] = r4[t + i * 256];
        lm = fmaxf(lm, fmaxf(fmaxf(vv[i].x, vv[i].y), fmaxf(vv[i].z, vv[i].w)));
    }
    #pragma unroll
    for (int off = 16; off; off >>= 1) lm = fmaxf(lm, __shfl_xor_sync(0xffffffffu, lm, off));
    int w = t >> 5;
    if ((t & 31) == 0) sh[w] = lm;
    __syncthreads();
    if (t < 32) {
        float a = (t < 8) ? sh[t] : -1e30f;
        #pragma unroll
        for (int off = 4; off; off >>= 1) a = fmaxf(a, __shfl_xor_sync(0xffffffffu, a, off));
        if (t == 0) sh[0] = a;
    }
    __syncthreads();
    float M = sh[0];
    __syncthreads();
    float s = 0.f;
    #pragma unroll
    for (int i = 0; i < 4; i++)
        s += __expf(vv[i].x - M) + __expf(vv[i].y - M) + __expf(vv[i].z - M) + __expf(vv[i].w - M);
    #pragma unroll
    for (int off = 16; off; off >>= 1) s += __shfl_xor_sync(0xffffffffu, s, off);
    if ((t & 31) == 0) sh[w] = s;
    __syncthreads();
    if (t == 0) {
        float tot = 0.f;
        #pragma unroll
        for (int i = 0; i < 8; i++) tot += sh[i];
        cmax[row] = M;
        cinv[row] = 1.f / tot;
    }
}

// ---------------- per-n renormalizer: rowsc[z,n] = 1/(1e-9 + sum_s w[s,n]) ----------------
__global__ void denom_kernel(const float* __restrict__ Rt, const float* __restrict__ cmax,
                             const float* __restrict__ cinv, float* __restrict__ rowsc) {
    __shared__ float sm[Ss], si[Ss];
    int z = blockIdx.y;
    int n = blockIdx.x * 256 + threadIdx.x;
    for (int i = threadIdx.x; i < Ss; i += 256) {
        sm[i] = cmax[z * Ss + i];
        si[i] = cinv[z * Ss + i];
    }
    __syncthreads();
    const float* R = Rt + (long long)z * Ss * Nn + n;
    float acc = 0.f;
    #pragma unroll 8
    for (int s = 0; s < Ss; s++)
        acc += __expf(R[(long long)s * Nn] - sm[s]) * si[s];
    rowsc[(long long)z * Nn + n] = 1.f / (1e-9f + acc);
}

// ---------------- generic tiled SGEMM, register-prefetch pipelined ----------------
// C[m,n] = sum_k A.B   A: row-major [M,K] (AT=false) or [K,M] (AT=true, lda = M-stride)
//                      B: [K,N] NN (BT=false, ldb) or [N,K] NT (BT=true, ldb)
// SOFT: A elements transformed exp(a - tmax[k]) * tinv[k] at smem-store (AT path only)
// EPI: 0 none | 1 +Res | 2 gelu(+bias) | 3 +bias+Res | 4 *rowsc[m]
template<int BM, int BN, int BK, int TM, int TN, bool AT, bool BT, bool SOFT, int EPI>
__global__ void __launch_bounds__((BM / TM) * (BN / TN))
gemm_k(int M, int N, int K,
       const float* __restrict__ A, int lda, long long sAo, long long sAi,
       const float* __restrict__ Bm, int ldb, long long sBo, long long sBi,
       float* __restrict__ C, int ldc, long long sCo, long long sCi,
       const float* __restrict__ Res,
       const float* __restrict__ bias,
       const float* __restrict__ tmax, const float* __restrict__ tinv,
       const float* __restrict__ rowsc,
       int inner, int sT, int sR) {
    constexpr int THREADS = (BM / TM) * (BN / TN);
    constexpr int KV = BK / 4, MV = BM / 4, NV = BN / 4;
    constexpr int A_IT = (BM * BK / 4) / THREADS;
    constexpr int B_IT = (BN * BK / 4) / THREADS;
    static_assert((BM * BK / 4) % THREADS == 0, "A tile mismatch");
    static_assert((BN * BK / 4) % THREADS == 0, "B tile mismatch");

    const int tid = threadIdx.x;
    const int z = blockIdx.z;
    const int zo = z / inner, zi = z - zo * inner;
    A  += zo * sAo + zi * sAi;
    Bm += zo * sBo + zi * sBi;
    C  += zo * sCo + zi * sCi;
    if (EPI == 1 || EPI == 3) Res += zo * sCo + zi * sCi;
    if (SOFT) { tmax += (long long)z * sT; tinv += (long long)z * sT; }
    if (EPI == 4) rowsc += (long long)z * sR;

    const int m0 = blockIdx.y * BM, n0 = blockIdx.x * BN;

    __shared__ float As[BK][BM];
    __shared__ float Bs[BK][BN];

    const int tx = tid % (BN / TN), ty = tid / (BN / TN);

    float4 ra[A_IT], rb[B_IT];

    auto loadA = [&](int k0) {
        #pragma unroll
        for (int i = 0; i < A_IT; i++) {
            int idx = tid + i * THREADS;
            if (!AT) {
                int m = idx / KV, kq = (idx % KV) * 4;
                ra[i] = *reinterpret_cast<const float4*>(A + (long long)(m0 + m) * lda + k0 + kq);
            } else {
                int k = idx / MV, mq = (idx % MV) * 4;
                ra[i] = *reinterpret_cast<const float4*>(A + (long long)(k0 + k) * lda + m0 + mq);
            }
        }
    };
    auto storeA = [&](int k0) {
        #pragma unroll
        for (int i = 0; i < A_IT; i++) {
            int idx = tid + i * THREADS;
            if (!AT) {
                int m = idx / KV, kq = (idx % KV) * 4;
                As[kq + 0][m] = ra[i].x; As[kq + 1][m] = ra[i].y;
                As[kq + 2][m] = ra[i].z; As[kq + 3][m] = ra[i].w;
            } else {
                int k = idx / MV, mq = (idx % MV) * 4;
                float4 v = ra[i];
                if (SOFT) {
                    float cm = tmax[k0 + k], ci = tinv[k0 + k];
                    v.x = __expf(v.x - cm) * ci; v.y = __expf(v.y - cm) * ci;
                    v.z = __expf(v.z - cm) * ci; v.w = __expf(v.w - cm) * ci;
                }
                *reinterpret_cast<float4*>(&As[k][mq]) = v;
            }
        }
    };
    auto loadB = [&](int k0) {
        #pragma unroll
        for (int i = 0; i < B_IT; i++) {
            int idx = tid + i * THREADS;
            if (!BT) {
                int k = idx / NV, nq = (idx % NV) * 4;
                rb[i] = *reinterpret_cast<const float4*>(Bm + (long long)(k0 + k) * ldb + n0 + nq);
            } else {
                int n = idx / KV, kq = (idx % KV) * 4;
                rb[i] = *reinterpret_cast<const float4*>(Bm + (long long)(n0 + n) * ldb + k0 + kq);
            }
        }
    };
    auto storeB = [&]() {
        #pragma unroll
        for (int i = 0; i < B_IT; i++) {
            int idx = tid + i * THREADS;
            if (!BT) {
                int k = idx / NV, nq = (idx % NV) * 4;
                *reinterpret_cast<float4*>(&Bs[k][nq]) = rb[i];
            } else {
                int n = idx / KV, kq = (idx % KV) * 4;
                Bs[kq + 0][n] = rb[i].x; Bs[kq + 1][n] = rb[i].y;
                Bs[kq + 2][n] = rb[i].z; Bs[kq + 3][n] = rb[i].w;
            }
        }
    };

    float acc[TM][TN];
    #pragma unroll
    for (int i = 0; i < TM; i++)
        #pragma unroll
        for (int j = 0; j < TN; j++) acc[i][j] = 0.f;

    // prologue: tile 0 into smem
    loadA(0); loadB(0);
    storeA(0); storeB();
    __syncthreads();

    for (int k0 = 0; k0 < K; k0 += BK) {
        const int kn = k0 + BK;
        const bool more = kn < K;
        if (more) { loadA(kn); loadB(kn); }   // prefetch next tile -> regs (overlaps compute)

        #pragma unroll
        for (int kk = 0; kk < BK; kk++) {
            float a[TM], b[TN];
            #pragma unroll
            for (int i = 0; i < TM; i += 4)
                *reinterpret_cast<float4*>(&a[i]) = *reinterpret_cast<const float4*>(&As[kk][ty * TM + i]);
            #pragma unroll
            for (int j = 0; j < TN; j += 4)
                *reinterpret_cast<float4*>(&b[j]) = *reinterpret_cast<const float4*>(&Bs[kk][tx * TN + j]);
            #pragma unroll
            for (int i = 0; i < TM; i++)
                #pragma unroll
                for (int j = 0; j < TN; j++)
                    acc[i][j] = fmaf(a[i], b[j], acc[i][j]);
        }
        __syncthreads();
        if (more) {
            storeA(kn); storeB();
            __syncthreads();
        }
    }

    #pragma unroll
    for (int i = 0; i < TM; i++) {
        int m = m0 + ty * TM + i;
        float rs = 1.f;
        if (EPI == 4) rs = rowsc[m];
        #pragma unroll
        for (int j = 0; j < TN; j += 4) {
            int n = n0 + tx * TN + j;
            float4 v = make_float4(acc[i][j], acc[i][j + 1], acc[i][j + 2], acc[i][j + 3]);
            if (EPI == 2 || EPI == 3) {
                float4 bb = *reinterpret_cast<const float4*>(bias + n);
                v.x += bb.x; v.y += bb.y; v.z += bb.z; v.w += bb.w;
            }
            if (EPI == 1 || EPI == 3) {
                float4 rr = *reinterpret_cast<const float4*>(Res + (long long)m * ldc + n);
                v.x += rr.x; v.y += rr.y; v.z += rr.z; v.w += rr.w;
            }
            if (EPI == 2) {
                v.x = gelu_f(v.x); v.y = gelu_f(v.y); v.z = gelu_f(v.z); v.w = gelu_f(v.w);
            }
            if (EPI == 4) { v.x *= rs; v.y *= rs; v.z *= rs; v.w *= rs; }
            *reinterpret_cast<float4*>(C + (long long)m * ldc + n) = v;
        }
    }
}

// ---------------- launch ----------------
static float* sym(const void* s) {
    void* p = nullptr;
    cudaGetSymbolAddress(&p, s);
    return (float*)p;
}

extern "C" void kernel_launch(void* const* d_in, const int* in_sizes, int n_in,
                              void* d_out, int out_size) {
    const float* F_in  = (const float*)d_in[0];
    const float* Mk    = (const float*)d_in[1];
    const float* Mv    = (const float*)d_in[2];
    const float* ln_g  = (const float*)d_in[3];
    const float* ln_b  = (const float*)d_in[4];
    const float* Wo    = (const float*)d_in[5];
    const float* ln2_g = (const float*)d_in[6];
    const float* ln2_b = (const float*)d_in[7];
    const float* W1    = (const float*)d_in[8];
    const float* b1    = (const float*)d_in[9];
    const float* W2    = (const float*)d_in[10];
    const float* b2    = (const float*)d_in[11];
    float* out = (float*)d_out;

    float* xln   = sym(g_xln);
    float* rt    = sym(g_rt);
    float* cmax  = sym(g_cmax);
    float* cinv  = sym(g_cinv);
    float* rowsc = sym(g_rowsc);
    float* ocat  = sym(g_ocat);
    float* ybuf  = sym(g_y);
    float* hln   = sym(g_hln);
    float* hact  = sym(g_hact);

    // 1. LN1
    ln_kernel<<<Bb * Nn, 256>>>(F_in, ln_g, ln_b, xln);

    // 2. scores transposed: Rt[z, s, n] = sum_dh Mk[h,s,dh] * xln[b,n,h*DH+dh]
    gemm_k<128, 128, 16, 8, 8, false, true, false, 0>
        <<<dim3(Nn / 128, Ss / 128, BH), 256>>>(
        Ss, Nn, DH,
        Mk, DH, 0LL, (long long)Ss * DH,
        xln, Dd, (long long)Nn * Dd, (long long)DH,
        rt, Nn, (long long)Hh * Ss * Nn, (long long)Ss * Nn,
        nullptr, nullptr, nullptr, nullptr, nullptr, Hh, 0, 0);

    // 3. softmax-over-N stats per (z, s)
    softmax_stats<<<BH * Ss, 256>>>(rt, cmax, cinv);

    // 4. per-n renormalizer
    denom_kernel<<<dim3(Nn / 256, BH), 256>>>(rt, cmax, cinv, rowsc);

    // 5. readout: Ocat[b, n, h*DH+d] = rowsc[z,n] * sum_s w[z,s,n] * Mv[h,s,d]
    gemm_k<128, 64, 16, 8, 4, true, false, true, 4>
        <<<dim3(1, Nn / 128, BH), 256>>>(
        Nn, DH, Ss,
        rt, Nn, (long long)Hh * Ss * Nn, (long long)Ss * Nn,
        Mv, DH, 0LL, (long long)Ss * DH,
        ocat, Dd, (long long)Nn * Dd, (long long)DH,
        nullptr, nullptr, cmax, cinv, rowsc, Hh, Ss, Nn);

    // 6. y = F_in + Ocat @ Wo^T
    gemm_k<128, 128, 16, 8, 8, false, true, false, 1>
        <<<dim3(Dd / 128, (Bb * Nn) / 128, 1), 256>>>(
        Bb * Nn, Dd, Dd,
        ocat, Dd, 0LL, 0LL,
        Wo, Dd, 0LL, 0LL,
        ybuf, Dd, 0LL, 0LL,
        F_in, nullptr, nullptr, nullptr, nullptr, 1, 0, 0);

    // 7. LN2
    ln_kernel<<<Bb * Nn, 256>>>(ybuf, ln2_g, ln2_b, hln);

    // 8. Hact = gelu(hln @ W1 + b1)
    gemm_k<128, 128, 16, 8, 8, false, false, false, 2>
        <<<dim3(DFF / 128, (Bb * Nn) / 128, 1), 256>>>(
        Bb * Nn, DFF, Dd,
        hln, Dd, 0LL, 0LL,
        W1, DFF, 0LL, 0LL,
        hact, DFF, 0LL, 0LL,
        nullptr, b1, nullptr, nullptr, nullptr, 1, 0, 0);

    // 9. out = ybuf + Hact @ W2 + b2
    gemm_k<128, 128, 16, 8, 8, false, false, false, 3>
        <<<dim3(Dd / 128, (Bb * Nn) / 128, 1), 256>>>(
        Bb * Nn, Dd, DFF,
        hact, DFF, 0LL, 0LL,
        W2, Dd, 0LL, 0LL,
        out, Dd, 0LL, 0LL,
        ybuf, b2, nullptr, nullptr, nullptr, 1, 0, 0);
}

// round 12
// speedup vs baseline: 2.1602x; 2.1602x over previous
#include <cuda_runtime.h>
#include <cuda_bf16.h>
#include <math.h>
#include <stdint.h>

// ---------------- problem constants ----------------
#define Bb   4
#define Nn   4096
#define Dd   1024
#define Hh   16
#define Ss   512
#define DH   64
#define DFF  4096
#define BH   (Bb*Hh)
#define Mrows (Bb*Nn)    // 16384

typedef __nv_bfloat16 bf16;

// ---------------- scratch (device globals; no mallocs allowed) ----------------
__device__ float g_xln [(size_t)Bb*Nn*Dd];        // 64 MB
__device__ float g_rt  [(size_t)BH*Ss*Nn];        // 512 MB
__device__ float g_cmax[BH*Ss];
__device__ float g_cinv[BH*Ss];
__device__ float g_rowsc[BH*Nn];
__device__ float g_y   [(size_t)Bb*Nn*Dd];        // 64 MB
// dual-bf16 activations
__device__ bf16 g_ocat_h[(size_t)Mrows*Dd],  g_ocat_l[(size_t)Mrows*Dd];
__device__ bf16 g_hln_h [(size_t)Mrows*Dd],  g_hln_l [(size_t)Mrows*Dd];
__device__ bf16 g_hact_h[(size_t)Mrows*DFF], g_hact_l[(size_t)Mrows*DFF];
// dual-bf16 weights, all stored [N, K]
__device__ bf16 g_wo_h[(size_t)Dd*Dd],   g_wo_l[(size_t)Dd*Dd];
__device__ bf16 g_w1_h[(size_t)DFF*Dd],  g_w1_l[(size_t)DFF*Dd];
__device__ bf16 g_w2_h[(size_t)Dd*DFF],  g_w2_l[(size_t)Dd*DFF];

// ---------------- helpers ----------------
__device__ __forceinline__ float gelu_f(float x) {
    return 0.5f * x * (1.f + erff(x * 0.70710678118654752f));
}
__device__ __forceinline__ uint32_t s2u(const void* p) {
    return (uint32_t)__cvta_generic_to_shared(p);
}
__device__ __forceinline__ void cpa16(void* dst, const void* src) {
    asm volatile("cp.async.cg.shared.global [%0], [%1], 16;\n" :: "r"(s2u(dst)), "l"(src));
}
__device__ __forceinline__ void cp_commit() { asm volatile("cp.async.commit_group;\n"); }
template<int NN_> __device__ __forceinline__ void cp_wait() {
    asm volatile("cp.async.wait_group %0;\n" :: "n"(NN_));
}
__device__ __forceinline__ void ldm4(uint32_t& r0, uint32_t& r1, uint32_t& r2, uint32_t& r3, uint32_t a) {
    asm volatile("ldmatrix.sync.aligned.m8n8.x4.shared.b16 {%0,%1,%2,%3}, [%4];\n"
        : "=r"(r0), "=r"(r1), "=r"(r2), "=r"(r3) : "r"(a));
}
__device__ __forceinline__ void mma16816(float* d, uint32_t a0, uint32_t a1, uint32_t a2, uint32_t a3,
                                         uint32_t b0, uint32_t b1) {
    asm volatile("mma.sync.aligned.m16n8k16.row.col.f32.bf16.bf16.f32 "
                 "{%0,%1,%2,%3},{%4,%5,%6,%7},{%8,%9},{%0,%1,%2,%3};\n"
        : "+f"(d[0]), "+f"(d[1]), "+f"(d[2]), "+f"(d[3])
        : "r"(a0), "r"(a1), "r"(a2), "r"(a3), "r"(b0), "r"(b1));
}
__device__ __forceinline__ void split2(float v, bf16& h, bf16& l) {
    h = __float2bfloat16(v);
    l = __float2bfloat16(v - __bfloat162float(h));
}

// ---------------- LayerNorm (DUAL=0: fp32 out; DUAL=1: hi/lo bf16 out) ----------------
template<int DUAL>
__global__ void ln_kernel(const float* __restrict__ x, const float* __restrict__ g,
                          const float* __restrict__ b, float* __restrict__ o,
                          bf16* __restrict__ oh, bf16* __restrict__ ol) {
    __shared__ float sh[64];
    long long row = blockIdx.x;
    const float4* xr = reinterpret_cast<const float4*>(x + row * Dd);
    int t = threadIdx.x;
    float4 v = xr[t];
    float s  = v.x + v.y + v.z + v.w;
    float ss = v.x*v.x + v.y*v.y + v.z*v.z + v.w*v.w;
    #pragma unroll
    for (int off = 16; off; off >>= 1) {
        s  += __shfl_xor_sync(0xffffffffu, s,  off);
        ss += __shfl_xor_sync(0xffffffffu, ss, off);
    }
    int w = t >> 5;
    if ((t & 31) == 0) { sh[w] = s; sh[32 + w] = ss; }
    __syncthreads();
    if (t < 32) {
        float a = (t < 8) ? sh[t]      : 0.f;
        float c = (t < 8) ? sh[32 + t] : 0.f;
        #pragma unroll
        for (int off = 4; off; off >>= 1) {
            a += __shfl_xor_sync(0xffffffffu, a, off);
            c += __shfl_xor_sync(0xffffffffu, c, off);
        }
        if (t == 0) { sh[0] = a; sh[1] = c; }
    }
    __syncthreads();
    float mean = sh[0] * (1.f / Dd);
    float var  = sh[1] * (1.f / Dd) - mean * mean;
    float r = rsqrtf(var + 1e-5f);
    float4 gv = reinterpret_cast<const float4*>(g)[t];
    float4 bv = reinterpret_cast<const float4*>(b)[t];
    float4 ov;
    ov.x = (v.x - mean) * r * gv.x + bv.x;
    ov.y = (v.y - mean) * r * gv.y + bv.y;
    ov.z = (v.z - mean) * r * gv.z + bv.z;
    ov.w = (v.w - mean) * r * gv.w + bv.w;
    if (DUAL == 0) {
        reinterpret_cast<float4*>(o + row * Dd)[t] = ov;
    } else {
        bf16 h0, l0, h1, l1, h2, l2, h3, l3;
        split2(ov.x, h0, l0); split2(ov.y, h1, l1);
        split2(ov.z, h2, l2); split2(ov.w, h3, l3);
        __nv_bfloat162* ph = reinterpret_cast<__nv_bfloat162*>(oh + row * Dd + t * 4);
        __nv_bfloat162* pl = reinterpret_cast<__nv_bfloat162*>(ol + row * Dd + t * 4);
        ph[0] = __nv_bfloat162(h0, h1); ph[1] = __nv_bfloat162(h2, h3);
        pl[0] = __nv_bfloat162(l0, l1); pl[1] = __nv_bfloat162(l2, l3);
    }
}

// ---------------- softmax stats over N (rows of Rt): one block per (z,s) ----------------
__global__ void softmax_stats(const float* __restrict__ Rt,
                              float* __restrict__ cmax, float* __restrict__ cinv) {
    __shared__ float sh[32];
    long long row = blockIdx.x;
    const float4* r4 = reinterpret_cast<const float4*>(Rt + row * Nn);
    int t = threadIdx.x;
    float4 vv[4];
    float lm = -1e30f;
    #pragma unroll
    for (int i = 0; i < 4; i++) {
        vv[i] = r4[t + i * 256];
        lm = fmaxf(lm, fmaxf(fmaxf(vv[i].x, vv[i].y), fmaxf(vv[i].z, vv[i].w)));
    }
    #pragma unroll
    for (int off = 16; off; off >>= 1) lm = fmaxf(lm, __shfl_xor_sync(0xffffffffu, lm, off));
    int w = t >> 5;
    if ((t & 31) == 0) sh[w] = lm;
    __syncthreads();
    if (t < 32) {
        float a = (t < 8) ? sh[t] : -1e30f;
        #pragma unroll
        for (int off = 4; off; off >>= 1) a = fmaxf(a, __shfl_xor_sync(0xffffffffu, a, off));
        if (t == 0) sh[0] = a;
    }
    __syncthreads();
    float M = sh[0];
    __syncthreads();
    float s = 0.f;
    #pragma unroll
    for (int i = 0; i < 4; i++)
        s += __expf(vv[i].x - M) + __expf(vv[i].y - M) + __expf(vv[i].z - M) + __expf(vv[i].w - M);
    #pragma unroll
    for (int off = 16; off; off >>= 1) s += __shfl_xor_sync(0xffffffffu, s, off);
    if ((t & 31) == 0) sh[w] = s;
    __syncthreads();
    if (t == 0) {
        float tot = 0.f;
        #pragma unroll
        for (int i = 0; i < 8; i++) tot += sh[i];
        cmax[row] = M;
        cinv[row] = 1.f / tot;
    }
}

// ---------------- per-n renormalizer ----------------
__global__ void denom_kernel(const float* __restrict__ Rt, const float* __restrict__ cmax,
                             const float* __restrict__ cinv, float* __restrict__ rowsc) {
    __shared__ float sm[Ss], si[Ss];
    int z = blockIdx.y;
    int n = blockIdx.x * 256 + threadIdx.x;
    for (int i = threadIdx.x; i < Ss; i += 256) {
        sm[i] = cmax[z * Ss + i];
        si[i] = cinv[z * Ss + i];
    }
    __syncthreads();
    const float* R = Rt + (long long)z * Ss * Nn + n;
    float acc = 0.f;
    #pragma unroll 8
    for (int s = 0; s < Ss; s++)
        acc += __expf(R[(long long)s * Nn] - sm[s]) * si[s];
    rowsc[(long long)z * Nn + n] = 1.f / (1e-9f + acc);
}

// ---------------- weight converters ----------------
__global__ void split_w(const float* __restrict__ W, bf16* __restrict__ oh, bf16* __restrict__ ol) {
    int i = blockIdx.x * 256 + threadIdx.x;
    float4 v = reinterpret_cast<const float4*>(W)[i];
    bf16 h0, l0, h1, l1, h2, l2, h3, l3;
    split2(v.x, h0, l0); split2(v.y, h1, l1); split2(v.z, h2, l2); split2(v.w, h3, l3);
    reinterpret_cast<__nv_bfloat162*>(oh)[i * 2 + 0] = __nv_bfloat162(h0, h1);
    reinterpret_cast<__nv_bfloat162*>(oh)[i * 2 + 1] = __nv_bfloat162(h2, h3);
    reinterpret_cast<__nv_bfloat162*>(ol)[i * 2 + 0] = __nv_bfloat162(l0, l1);
    reinterpret_cast<__nv_bfloat162*>(ol)[i * 2 + 1] = __nv_bfloat162(l2, l3);
}

// transpose + split: W [K,N] fp32 -> out [N,K] hi/lo bf16.  block 32x8, tile 32x32
__global__ void tsplit_w(const float* __restrict__ W, bf16* __restrict__ oh, bf16* __restrict__ ol,
                         int K, int N) {
    __shared__ float t[32][33];
    int k0 = blockIdx.y * 32, n0 = blockIdx.x * 32;
    int tx = threadIdx.x, ty = threadIdx.y;
    #pragma unroll
    for (int i = ty; i < 32; i += 8)
        t[i][tx] = W[(size_t)(k0 + i) * N + n0 + tx];
    __syncthreads();
    #pragma unroll
    for (int i = ty; i < 32; i += 8) {
        float v = t[tx][i];                       // = W[k0+tx][n0+i]
        bf16 h, l; split2(v, h, l);
        size_t o = (size_t)(n0 + i) * K + k0 + tx;
        oh[o] = h; ol[o] = l;
    }
}

// ---------------- fp32 SGEMM (attention path), register-prefetch pipelined ----------------
// OUT: 0 = fp32 C; 1 = dual bf16 Ch/Cl
template<int BM, int BN, int BK, int TM, int TN, bool AT, bool BT, bool SOFT, int EPI, int OUT>
__global__ void __launch_bounds__((BM / TM) * (BN / TN))
gemm_k(int M, int N, int K,
       const float* __restrict__ A, int lda, long long sAo, long long sAi,
       const float* __restrict__ Bm, int ldb, long long sBo, long long sBi,
       float* __restrict__ C, bf16* __restrict__ Ch, bf16* __restrict__ Cl,
       int ldc, long long sCo, long long sCi,
       const float* __restrict__ Res,
       const float* __restrict__ bias,
       const float* __restrict__ tmax, const float* __restrict__ tinv,
       const float* __restrict__ rowsc,
       int inner, int sT, int sR) {
    constexpr int THREADS = (BM / TM) * (BN / TN);
    constexpr int KV = BK / 4, MV = BM / 4, NV = BN / 4;
    constexpr int A_IT = (BM * BK / 4) / THREADS;
    constexpr int B_IT = (BN * BK / 4) / THREADS;

    const int tid = threadIdx.x;
    const int z = blockIdx.z;
    const int zo = z / inner, zi = z - zo * inner;
    A  += zo * sAo + zi * sAi;
    Bm += zo * sBo + zi * sBi;
    long long coff = zo * sCo + zi * sCi;
    if (OUT == 0) C += coff; else { Ch += coff; Cl += coff; }
    if (EPI == 1 || EPI == 3) Res += coff;
    if (SOFT) { tmax += (long long)z * sT; tinv += (long long)z * sT; }
    if (EPI == 4) rowsc += (long long)z * sR;

    const int m0 = blockIdx.y * BM, n0 = blockIdx.x * BN;

    __shared__ float As[BK][BM];
    __shared__ float Bs[BK][BN];

    const int tx = tid % (BN / TN), ty = tid / (BN / TN);

    float4 ra[A_IT], rb[B_IT];

    auto loadA = [&](int k0) {
        #pragma unroll
        for (int i = 0; i < A_IT; i++) {
            int idx = tid + i * THREADS;
            if (!AT) {
                int m = idx / KV, kq = (idx % KV) * 4;
                ra[i] = *reinterpret_cast<const float4*>(A + (long long)(m0 + m) * lda + k0 + kq);
            } else {
                int k = idx / MV, mq = (idx % MV) * 4;
                ra[i] = *reinterpret_cast<const float4*>(A + (long long)(k0 + k) * lda + m0 + mq);
            }
        }
    };
    auto storeA = [&](int k0) {
        #pragma unroll
        for (int i = 0; i < A_IT; i++) {
            int idx = tid + i * THREADS;
            if (!AT) {
                int m = idx / KV, kq = (idx % KV) * 4;
                As[kq + 0][m] = ra[i].x; As[kq + 1][m] = ra[i].y;
                As[kq + 2][m] = ra[i].z; As[kq + 3][m] = ra[i].w;
            } else {
                int k = idx / MV, mq = (idx % MV) * 4;
                float4 v = ra[i];
                if (SOFT) {
                    float cm = tmax[k0 + k], ci = tinv[k0 + k];
                    v.x = __expf(v.x - cm) * ci; v.y = __expf(v.y - cm) * ci;
                    v.z = __expf(v.z - cm) * ci; v.w = __expf(v.w - cm) * ci;
                }
                *reinterpret_cast<float4*>(&As[k][mq]) = v;
            }
        }
    };
    auto loadB = [&](int k0) {
        #pragma unroll
        for (int i = 0; i < B_IT; i++) {
            int idx = tid + i * THREADS;
            if (!BT) {
                int k = idx / NV, nq = (idx % NV) * 4;
                rb[i] = *reinterpret_cast<const float4*>(Bm + (long long)(k0 + k) * ldb + n0 + nq);
            } else {
                int n = idx / KV, kq = (idx % KV) * 4;
                rb[i] = *reinterpret_cast<const float4*>(Bm + (long long)(n0 + n) * ldb + k0 + kq);
            }
        }
    };
    auto storeB = [&]() {
        #pragma unroll
        for (int i = 0; i < B_IT; i++) {
            int idx = tid + i * THREADS;
            if (!BT) {
                int k = idx / NV, nq = (idx % NV) * 4;
                *reinterpret_cast<float4*>(&Bs[k][nq]) = rb[i];
            } else {
                int n = idx / KV, kq = (idx % KV) * 4;
                Bs[kq + 0][n] = rb[i].x; Bs[kq + 1][n] = rb[i].y;
                Bs[kq + 2][n] = rb[i].z; Bs[kq + 3][n] = rb[i].w;
            }
        }
    };

    float acc[TM][TN];
    #pragma unroll
    for (int i = 0; i < TM; i++)
        #pragma unroll
        for (int j = 0; j < TN; j++) acc[i][j] = 0.f;

    loadA(0); loadB(0);
    storeA(0); storeB();
    __syncthreads();

    for (int k0 = 0; k0 < K; k0 += BK) {
        const int kn = k0 + BK;
        const bool more = kn < K;
        if (more) { loadA(kn); loadB(kn); }

        #pragma unroll
        for (int kk = 0; kk < BK; kk++) {
            float a[TM], b[TN];
            #pragma unroll
            for (int i = 0; i < TM; i += 4)
                *reinterpret_cast<float4*>(&a[i]) = *reinterpret_cast<const float4*>(&As[kk][ty * TM + i]);
            #pragma unroll
            for (int j = 0; j < TN; j += 4)
                *reinterpret_cast<float4*>(&b[j]) = *reinterpret_cast<const float4*>(&Bs[kk][tx * TN + j]);
            #pragma unroll
            for (int i = 0; i < TM; i++)
                #pragma unroll
                for (int j = 0; j < TN; j++)
                    acc[i][j] = fmaf(a[i], b[j], acc[i][j]);
        }
        __syncthreads();
        if (more) {
            storeA(kn); storeB();
            __syncthreads();
        }
    }

    #pragma unroll
    for (int i = 0; i < TM; i++) {
        int m = m0 + ty * TM + i;
        float rs = 1.f;
        if (EPI == 4) rs = rowsc[m];
        #pragma unroll
        for (int j = 0; j < TN; j += 4) {
            int n = n0 + tx * TN + j;
            float4 v = make_float4(acc[i][j], acc[i][j + 1], acc[i][j + 2], acc[i][j + 3]);
            if (EPI == 2 || EPI == 3) {
                float4 bb = *reinterpret_cast<const float4*>(bias + n);
                v.x += bb.x; v.y += bb.y; v.z += bb.z; v.w += bb.w;
            }
            if (EPI == 1 || EPI == 3) {
                float4 rr = *reinterpret_cast<const float4*>(Res + (long long)m * ldc + n);
                v.x += rr.x; v.y += rr.y; v.z += rr.z; v.w += rr.w;
            }
            if (EPI == 2) {
                v.x = gelu_f(v.x); v.y = gelu_f(v.y); v.z = gelu_f(v.z); v.w = gelu_f(v.w);
            }
            if (EPI == 4) { v.x *= rs; v.y *= rs; v.z *= rs; v.w *= rs; }
            if (OUT == 0) {
                *reinterpret_cast<float4*>(C + (long long)m * ldc + n) = v;
            } else {
                bf16 h0, l0, h1, l1, h2, l2, h3, l3;
                split2(v.x, h0, l0); split2(v.y, h1, l1);
                split2(v.z, h2, l2); split2(v.w, h3, l3);
                __nv_bfloat162* ph = reinterpret_cast<__nv_bfloat162*>(Ch + (long long)m * ldc + n);
                __nv_bfloat162* pl = reinterpret_cast<__nv_bfloat162*>(Cl + (long long)m * ldc + n);
                ph[0] = __nv_bfloat162(h0, h1); ph[1] = __nv_bfloat162(h2, h3);
                pl[0] = __nv_bfloat162(l0, l1); pl[1] = __nv_bfloat162(l2, l3);
            }
        }
    }
}

// ---------------- bf16-split tensor-core GEMM: C[M,N] = A[M,K] . W[N,K]^T ----------------
// A, W given as hi/lo bf16 pairs. acc = Ah*Wh + Ah*Wl + Al*Wh (fp32 accum).
// EPI: 1 = +Res, fp32 C | 2 = gelu(v+bias), dual-bf16 Ch/Cl | 3 = +bias+Res, fp32 C
#define TCS   40            // smem row stride in halves (32 data + 8 pad)
#define TILEH (128*TCS)     // halves per tile buffer

template<int EPI>
__global__ void __launch_bounds__(256)
gemm_tc(int M, int N, int K,
        const bf16* __restrict__ Ah, const bf16* __restrict__ Al,
        const bf16* __restrict__ Bh, const bf16* __restrict__ Bl,
        float* __restrict__ C, bf16* __restrict__ Ch, bf16* __restrict__ Cl,
        const float* __restrict__ Res, const float* __restrict__ bias, int ldc) {
    extern __shared__ bf16 dsm[];
    const int tid = threadIdx.x, lane = tid & 31, wid = tid >> 5;
    const int m0 = blockIdx.y * 128, n0 = blockIdx.x * 128;
    const int wm = (wid >> 2) * 64, wn = (wid & 3) * 32;

    auto tile = [&](int s, int b) -> bf16* { return dsm + (s * 4 + b) * TILEH; };

    auto issue = [&](int kt, int s) {
        int k0 = kt * 32;
        bf16 *tAh = tile(s, 0), *tAl = tile(s, 1), *tBh = tile(s, 2), *tBl = tile(s, 3);
        #pragma unroll
        for (int i = 0; i < 2; i++) {
            int idx = tid + i * 256;
            int row = idx >> 2, off = (idx & 3) * 8;
            size_t ga = (size_t)(m0 + row) * K + k0 + off;
            size_t gb = (size_t)(n0 + row) * K + k0 + off;
            cpa16(tAh + row * TCS + off, Ah + ga);
            cpa16(tAl + row * TCS + off, Al + ga);
            cpa16(tBh + row * TCS + off, Bh + gb);
            cpa16(tBl + row * TCS + off, Bl + gb);
        }
        cp_commit();
    };

    float acc[4][4][4];
    #pragma unroll
    for (int i = 0; i < 4; i++)
        #pragma unroll
        for (int j = 0; j < 4; j++)
            #pragma unroll
            for (int c = 0; c < 4; c++) acc[i][j][c] = 0.f;

    const int T = K / 32;
    issue(0, 0);
    for (int t = 0; t < T; t++) {
        if (t + 1 < T) { issue(t + 1, (t + 1) & 1); cp_wait<1>(); }
        else           { cp_wait<0>(); }
        __syncthreads();
        int s = t & 1;
        bf16 *tAh = tile(s, 0), *tAl = tile(s, 1), *tBh = tile(s, 2), *tBl = tile(s, 3);
        const int grp = lane >> 3, r = lane & 7;
        #pragma unroll
        for (int kh = 0; kh < 2; kh++) {
            const int kb = kh * 16;
            uint32_t bh[4][2], bl[4][2];
            #pragma unroll
            for (int p = 0; p < 2; p++) {
                int boff = (wn + p * 16 + ((grp >> 1) << 3) + r) * TCS + kb + ((grp & 1) << 3);
                uint32_t r0, r1, r2, r3;
                ldm4(r0, r1, r2, r3, s2u(tBh + boff));
                bh[2*p][0] = r0; bh[2*p][1] = r1; bh[2*p+1][0] = r2; bh[2*p+1][1] = r3;
                ldm4(r0, r1, r2, r3, s2u(tBl + boff));
                bl[2*p][0] = r0; bl[2*p][1] = r1; bl[2*p+1][0] = r2; bl[2*p+1][1] = r3;
            }
            #pragma unroll
            for (int mt = 0; mt < 4; mt++) {
                int aoff = (wm + mt * 16 + ((grp & 1) << 3) + r) * TCS + kb + ((grp >> 1) << 3);
                uint32_t a0, a1, a2, a3, l0, l1, l2, l3;
                ldm4(a0, a1, a2, a3, s2u(tAh + aoff));
                ldm4(l0, l1, l2, l3, s2u(tAl + aoff));
                #pragma unroll
                for (int nt = 0; nt < 4; nt++) {
                    mma16816(acc[mt][nt], a0, a1, a2, a3, bh[nt][0], bh[nt][1]);
                    mma16816(acc[mt][nt], a0, a1, a2, a3, bl[nt][0], bl[nt][1]);
                    mma16816(acc[mt][nt], l0, l1, l2, l3, bh[nt][0], bh[nt][1]);
                }
            }
        }
        __syncthreads();
    }

    #pragma unroll
    for (int mt = 0; mt < 4; mt++) {
        #pragma unroll
        for (int half = 0; half < 2; half++) {
            int m = m0 + wm + mt * 16 + (lane >> 2) + half * 8;
            #pragma unroll
            for (int nt = 0; nt < 4; nt++) {
                int n = n0 + wn + nt * 8 + (lane & 3) * 2;
                float v0 = acc[mt][nt][half * 2 + 0];
                float v1 = acc[mt][nt][half * 2 + 1];
                if (EPI == 2 || EPI == 3) {
                    float2 bb = *reinterpret_cast<const float2*>(bias + n);
                    v0 += bb.x; v1 += bb.y;
                }
                if (EPI == 1 || EPI == 3) {
                    float2 rr = *reinterpret_cast<const float2*>(Res + (size_t)m * ldc + n);
                    v0 += rr.x; v1 += rr.y;
                }
                if (EPI == 2) {
                    v0 = gelu_f(v0); v1 = gelu_f(v1);
                    bf16 h0, lo0, h1, lo1;
                    split2(v0, h0, lo0); split2(v1, h1, lo1);
                    *reinterpret_cast<__nv_bfloat162*>(Ch + (size_t)m * ldc + n) = __nv_bfloat162(h0, h1);
                    *reinterpret_cast<__nv_bfloat162*>(Cl + (size_t)m * ldc + n) = __nv_bfloat162(lo0, lo1);
                } else {
                    *reinterpret_cast<float2*>(C + (size_t)m * ldc + n) = make_float2(v0, v1);
                }
            }
        }
    }
}

// ---------------- launch ----------------
static float* symf(const void* s) { void* p = nullptr; cudaGetSymbolAddress(&p, s); return (float*)p; }
static bf16*  symb(const void* s) { void* p = nullptr; cudaGetSymbolAddress(&p, s); return (bf16*)p; }

extern "C" void kernel_launch(void* const* d_in, const int* in_sizes, int n_in,
                              void* d_out, int out_size) {
    const float* F_in  = (const float*)d_in[0];
    const float* Mk    = (const float*)d_in[1];
    const float* Mv    = (const float*)d_in[2];
    const float* ln_g  = (const float*)d_in[3];
    const float* ln_b  = (const float*)d_in[4];
    const float* Wo    = (const float*)d_in[5];
    const float* ln2_g = (const float*)d_in[6];
    const float* ln2_b = (const float*)d_in[7];
    const float* W1    = (const float*)d_in[8];
    const float* b1    = (const float*)d_in[9];
    const float* W2    = (const float*)d_in[10];
    const float* b2    = (const float*)d_in[11];
    float* out = (float*)d_out;

    float* xln   = symf(g_xln);
    float* rt    = symf(g_rt);
    float* cmax  = symf(g_cmax);
    float* cinv  = symf(g_cinv);
    float* rowsc = symf(g_rowsc);
    float* ybuf  = symf(g_y);
    bf16 *ocat_h = symb(g_ocat_h), *ocat_l = symb(g_ocat_l);
    bf16 *hln_h  = symb(g_hln_h),  *hln_l  = symb(g_hln_l);
    bf16 *hact_h = symb(g_hact_h), *hact_l = symb(g_hact_l);
    bf16 *wo_h = symb(g_wo_h), *wo_l = symb(g_wo_l);
    bf16 *w1_h = symb(g_w1_h), *w1_l = symb(g_w1_l);
    bf16 *w2_h = symb(g_w2_h), *w2_l = symb(g_w2_l);

    const int TC_SMEM = 2 * 4 * TILEH * (int)sizeof(bf16);   // 81920 bytes
    cudaFuncSetAttribute(gemm_tc<1>, cudaFuncAttributeMaxDynamicSharedMemorySize, TC_SMEM);
    cudaFuncSetAttribute(gemm_tc<2>, cudaFuncAttributeMaxDynamicSharedMemorySize, TC_SMEM);
    cudaFuncSetAttribute(gemm_tc<3>, cudaFuncAttributeMaxDynamicSharedMemorySize, TC_SMEM);

    // 0. weight conversions (hi/lo bf16; W1/W2 also transposed to [N,K])
    split_w<<<(Dd * Dd) / 4 / 256, 256>>>(Wo, wo_h, wo_l);
    tsplit_w<<<dim3(DFF / 32, Dd / 32), dim3(32, 8)>>>(W1, w1_h, w1_l, Dd, DFF);
    tsplit_w<<<dim3(Dd / 32, DFF / 32), dim3(32, 8)>>>(W2, w2_h, w2_l, DFF, Dd);

    // 1. LN1 (fp32 out)
    ln_kernel<0><<<Bb * Nn, 256>>>(F_in, ln_g, ln_b, xln, nullptr, nullptr);

    // 2. scores transposed: Rt[z,s,n] (fp32 SGEMM)
    gemm_k<128, 128, 16, 8, 8, false, true, false, 0, 0>
        <<<dim3(Nn / 128, Ss / 128, BH), 256>>>(
        Ss, Nn, DH,
        Mk, DH, 0LL, (long long)Ss * DH,
        xln, Dd, (long long)Nn * Dd, (long long)DH,
        rt, nullptr, nullptr, Nn, (long long)Hh * Ss * Nn, (long long)Ss * Nn,
        nullptr, nullptr, nullptr, nullptr, nullptr, Hh, 0, 0);

    // 3. softmax-over-N stats
    softmax_stats<<<BH * Ss, 256>>>(rt, cmax, cinv);

    // 4. per-n renormalizer
    denom_kernel<<<dim3(Nn / 256, BH), 256>>>(rt, cmax, cinv, rowsc);

    // 5. readout -> ocat (dual bf16 out)
    gemm_k<128, 64, 16, 8, 4, true, false, true, 4, 1>
        <<<dim3(1, Nn / 128, BH), 256>>>(
        Nn, DH, Ss,
        rt, Nn, (long long)Hh * Ss * Nn, (long long)Ss * Nn,
        Mv, DH, 0LL, (long long)Ss * DH,
        nullptr, ocat_h, ocat_l, Dd, (long long)Nn * Dd, (long long)DH,
        nullptr, nullptr, cmax, cinv, rowsc, Hh, Ss, Nn);

    // 6. y = F_in + Ocat @ Wo^T   (TC)
    gemm_tc<1><<<dim3(Dd / 128, Mrows / 128), 256, TC_SMEM>>>(
        Mrows, Dd, Dd, ocat_h, ocat_l, wo_h, wo_l,
        ybuf, nullptr, nullptr, F_in, nullptr, Dd);

    // 7. LN2 (dual bf16 out)
    ln_kernel<1><<<Bb * Nn, 256>>>(ybuf, ln2_g, ln2_b, nullptr, hln_h, hln_l);

    // 8. hact = gelu(hln @ W1 + b1)   (TC, dual bf16 out)
    gemm_tc<2><<<dim3(DFF / 128, Mrows / 128), 256, TC_SMEM>>>(
        Mrows, DFF, Dd, hln_h, hln_l, w1_h, w1_l,
        nullptr, hact_h, hact_l, nullptr, b1, DFF);

    // 9. out = ybuf + hact @ W2 + b2   (TC)
    gemm_tc<3><<<dim3(Dd / 128, Mrows / 128), 256, TC_SMEM>>>(
        Mrows, Dd, DFF, hact_h, hact_l, w2_h, w2_l,
        out, nullptr, nullptr, ybuf, b2, Dd);
}